// round 6
// baseline (speedup 1.0000x reference)
#include <cuda_runtime.h>
#include <cuda_bf16.h>

// SpikeAmplifier: IF neuron with lateral amplification.
// input: (T=128, N=16, C=1, J=8192) f32 ; lateral_weight: (J=8192,) f32
// out:   (T, N, C, J) f32 spikes.
// Per neuron, sequential in t:
//   h = y_prev * (h + w[j]); v += x_t + h; s = (v >= 1); v = s ? 0 : v; emit s.
//
// Strategy (R6):
//  - float4 lanes -> 4x fewer LDG/STG instructions (LSU issue was a co-limiter).
//  - grid 1024 x 32 -> ~6.9 CTAs/SM, balanced (256x128 had a 2:1 CTA tail).
//  - input loads DEFAULT-cached: the graph replays re-read the same 64MB input;
//    it fits in the 126MB L2 and stays resident IF we don't mark it streaming.
//  - output stores .cs (evict-first): stream to DRAM, don't evict the input.
//    Steady-state DRAM traffic ~= 67MB writes; reads served from L2.
//  - CH=8 double-buffered prefetch hides L2/DRAM latency under the serial
//    per-neuron dependency chain.

constexpr int T_STEPS = 128;
constexpr int J_DIM   = 8192;
constexpr int NCJ     = 16 * J_DIM;          // 131072 neurons
constexpr int S4      = NCJ / 4;             // 32768 float4 lanes per timestep
constexpr int J4      = J_DIM / 4;           // 2048 float4 weights
constexpr int CH      = 8;                   // prefetch depth (timesteps)

__global__ __launch_bounds__(32)
void spike_amplifier_kernel(const float4* __restrict__ in,
                            const float4* __restrict__ w4,
                            float4* __restrict__ out) {
    const int idx = blockIdx.x * 32 + threadIdx.x;   // 0 .. S4-1
    const float4 wv = __ldg(w4 + (idx & (J4 - 1)));

    float h0 = 0.f, h1 = 0.f, h2 = 0.f, h3 = 0.f;
    float v0 = 0.f, v1 = 0.f, v2 = 0.f, v3 = 0.f;
    float y0 = 0.f, y1 = 0.f, y2 = 0.f, y3 = 0.f;

    float4 buf[CH], nxt[CH];

    // Prime: chunk 0 loads (default policy -> L2-resident across graph replays).
    #pragma unroll
    for (int c = 0; c < CH; c++)
        buf[c] = in[(size_t)c * S4 + idx];

    #pragma unroll 1
    for (int tc = 0; tc < T_STEPS; tc += CH) {
        // Prefetch next chunk while this one computes.
        if (tc + CH < T_STEPS) {
            #pragma unroll
            for (int c = 0; c < CH; c++)
                nxt[c] = in[(size_t)(tc + CH + c) * S4 + idx];
        }

        #pragma unroll
        for (int c = 0; c < CH; c++) {
            h0 = y0 * (h0 + wv.x);
            h1 = y1 * (h1 + wv.y);
            h2 = y2 * (h2 + wv.z);
            h3 = y3 * (h3 + wv.w);
            v0 += buf[c].x + h0;
            v1 += buf[c].y + h1;
            v2 += buf[c].z + h2;
            v3 += buf[c].w + h3;
            y0 = (v0 >= 1.0f) ? 1.0f : 0.0f;
            y1 = (v1 >= 1.0f) ? 1.0f : 0.0f;
            y2 = (v2 >= 1.0f) ? 1.0f : 0.0f;
            y3 = (v3 >= 1.0f) ? 1.0f : 0.0f;
            v0 = (y0 != 0.0f) ? 0.0f : v0;
            v1 = (y1 != 0.0f) ? 0.0f : v1;
            v2 = (y2 != 0.0f) ? 0.0f : v2;
            v3 = (y3 != 0.0f) ? 0.0f : v3;

            float4 o;
            o.x = y0; o.y = y1; o.z = y2; o.w = y3;
            __stcs(out + (size_t)(tc + c) * S4 + idx, o);
        }

        #pragma unroll
        for (int c = 0; c < CH; c++)
            buf[c] = nxt[c];
    }
}

extern "C" void kernel_launch(void* const* d_in, const int* in_sizes, int n_in,
                              void* d_out, int out_size) {
    const float4* in = (const float4*)d_in[0];   // (T,N,C,J) f32
    const float4* w4 = (const float4*)d_in[1];   // (J,) f32
    float4* out = (float4*)d_out;                // (T,N,C,J) f32

    const int threads = 32;
    const int blocks  = S4 / threads;            // 1024
    spike_amplifier_kernel<<<blocks, threads>>>(in, w4, out);
}

// round 8
// speedup vs baseline: 1.1255x; 1.1255x over previous
#include <cuda_runtime.h>
#include <cuda_bf16.h>

// SpikeAmplifier: IF neuron with lateral amplification.
// input: (T=128, N=16, C=1, J=8192) f32 ; lateral_weight: (J=8192,) f32
// out:   (T, N, C, J) f32 spikes.
// Per neuron, sequential in t:
//   h = y_prev * (h + w[j]); v += x_t + h; s = (v >= 1); v = s ? 0 : v; emit s.
//
// R7 strategy: warp count is the observable that tracks perf (4096w beat 1024w).
//  - float2 lanes: 65536 threads = 2048 warps (2x R6), half the LDG/STG of scalar.
//  - grid 2048 x 32: 13.8 CTAs/SM, ~1% tail imbalance.
//  - CH=16 double-buffered prefetch: 8MB in flight -> ~2MB on the DRAM-miss side,
//    above the BW*latency product (~1.8MB), to push DRAM busy% up.
//  - default-cached reads (L2 absorbs ~75% of reads across graph replays),
//    .cs streaming stores.

constexpr int T_STEPS = 128;
constexpr int J_DIM   = 8192;
constexpr int NCJ     = 16 * J_DIM;          // 131072 neurons
constexpr int S2      = NCJ / 2;             // 65536 float2 lanes per timestep
constexpr int J2      = J_DIM / 2;           // 4096 float2 weights
constexpr int CH      = 16;                  // prefetch depth (timesteps)

__global__ __launch_bounds__(32)
void spike_amplifier_kernel(const float2* __restrict__ in,
                            const float2* __restrict__ w2,
                            float2* __restrict__ out) {
    const int idx = blockIdx.x * 32 + threadIdx.x;   // 0 .. S2-1
    const float2 wv = __ldg(w2 + (idx & (J2 - 1)));

    float h0 = 0.f, h1 = 0.f;
    float v0 = 0.f, v1 = 0.f;
    float y0 = 0.f, y1 = 0.f;

    float2 buf[CH], nxt[CH];

    // Prime: chunk 0 loads.
    #pragma unroll
    for (int c = 0; c < CH; c++)
        buf[c] = in[(size_t)c * S2 + idx];

    #pragma unroll 1
    for (int tc = 0; tc < T_STEPS; tc += CH) {
        // Prefetch next chunk while this one computes.
        if (tc + CH < T_STEPS) {
            #pragma unroll
            for (int c = 0; c < CH; c++)
                nxt[c] = in[(size_t)(tc + CH + c) * S2 + idx];
        }

        #pragma unroll
        for (int c = 0; c < CH; c++) {
            h0 = y0 * (h0 + wv.x);
            h1 = y1 * (h1 + wv.y);
            v0 += buf[c].x + h0;
            v1 += buf[c].y + h1;
            y0 = (v0 >= 1.0f) ? 1.0f : 0.0f;
            y1 = (v1 >= 1.0f) ? 1.0f : 0.0f;
            v0 = (y0 != 0.0f) ? 0.0f : v0;
            v1 = (y1 != 0.0f) ? 0.0f : v1;

            float2 o;
            o.x = y0; o.y = y1;
            __stcs(out + (size_t)(tc + c) * S2 + idx, o);
        }

        #pragma unroll
        for (int c = 0; c < CH; c++)
            buf[c] = nxt[c];
    }
}

extern "C" void kernel_launch(void* const* d_in, const int* in_sizes, int n_in,
                              void* d_out, int out_size) {
    const float2* in = (const float2*)d_in[0];   // (T,N,C,J) f32
    const float2* w2 = (const float2*)d_in[1];   // (J,) f32
    float2* out = (float2*)d_out;                // (T,N,C,J) f32

    const int threads = 32;
    const int blocks  = S2 / threads;            // 2048
    spike_amplifier_kernel<<<blocks, threads>>>(in, w2, out);
}